// round 8
// baseline (speedup 1.0000x reference)
#include <cuda_runtime.h>
#include <cstdint>

// ---------------- problem constants ----------------
#define N_CB 4
#define M_CODES 512
#define D_DIM 32
#define T_POS 65536

// output layout (float32, reference tuple order, flattened+concatenated)
#define OFF_ZQ   0ULL
#define OFF_LOSS 8388608ULL
#define OFF_PERP 8388609ULL
#define OFF_IDX  8388610ULL
#define OFF_EMB  8650754ULL
#define OFF_CNT  8716290ULL
#define OFF_W    8718338ULL

// fragment-permuted slot: d = kt*8 + 4*h + q4  ->  slot = q4*8 + kt*2 + h
#define SLOT(d) (((d) & 3) * 8 + ((d) >> 3) * 2 + (((d) >> 2) & 1))

// ---------------- smem layout (float offsets), stride 36 rows ----------------
#define SXP_F   0        // x  [128 pos][36]  (permuted)   4608
#define SE_F    4608     // e  [512 code][36] (permuted)  18432
#define SESQ_F  23040    // esq[512]
#define SXSQ_F  23552    // xsq[128]
#define SSAB_F  23680    // sum|x| [128]
#define SBEST_F 23808    // u64[128] packed (dist,code)
#define SQ_F    24064    // queue u32[1536]
#define SWS_F   25600    // warp loss partials [8]
#define SMEM_FLOATS 25608
#define SMEM_BYTES (SMEM_FLOATS * 4)   // 102432 -> 2 CTAs/SM

#define FLT_BIG 3.402823466e38f
#define MARG_COEF 1.6e-4f
#define MARG_ABS  5e-5f
#define QCAP 1536

// ---------------- scratch ----------------
__device__ int    g_counts[N_CB * M_CODES];
__device__ float4 g_dw4[N_CB * M_CODES * 8];
__device__ double g_loss;

// ---------------- kernel 0: zero scratch ----------------
__global__ void vq_zero(float* __restrict__ out) {
    int i = blockIdx.x * blockDim.x + threadIdx.x;
    float* dw = (float*)g_dw4;
    if (i < N_CB * M_CODES * D_DIM) dw[i] = 0.0f;
    if (i < N_CB * M_CODES)         g_counts[i] = 0;
    if (i == 0) { g_loss = 0.0; out[OFF_PERP] = 0.0f; }
}

// ---------------- kernel 1: seeded single-pass tf32 mma + queued exact recheck ----------------
__global__ void __launch_bounds__(256) vq_main(const float* __restrict__ x,
                                               const float* __restrict__ emb,
                                               float* __restrict__ out) {
    extern __shared__ float sm[];
    __shared__ int qn;
    float* sX   = sm + SXP_F;
    float* sE   = sm + SE_F;
    float* sEsq = sm + SESQ_F;
    float* sXsq = sm + SXSQ_F;
    float* sSab = sm + SSAB_F;
    unsigned long long* sBest = (unsigned long long*)(sm + SBEST_F);
    unsigned int* sQ = (unsigned int*)(sm + SQ_F);
    float* sWs  = sm + SWS_F;

    const int n    = blockIdx.y;
    const int tile = blockIdx.x;
    const int tid  = threadIdx.x;
    const int w    = tid >> 5;
    const int lane = tid & 31;
    const int g    = lane >> 2;
    const int q4   = lane & 3;

    // ---- fill x tile (permuted layout) ----
    for (int i = tid; i < 128 * D_DIM; i += 256) {
        int d = i >> 7, p = i & 127;
        int t = tile * 128 + p;
        sX[p * 36 + SLOT(d)] = x[(size_t)(t >> 6) * 8192 + (size_t)n * 2048 + d * 64 + (t & 63)];
    }
    // ---- fill codebook (permuted layout) ----
    const float* en = emb + (size_t)n * M_CODES * D_DIM;
    for (int i = tid; i < M_CODES * D_DIM; i += 256) {
        int m = i >> 5, d = i & 31;
        sE[m * 36 + SLOT(d)] = en[i];
    }
    if (tid == 0) qn = 0;
    __syncthreads();

    // ---- esq: ascending-d fmaf chain (compile-time slot gather) ----
    for (int c = tid; c < M_CODES; c += 256) {
        const float* er = sE + c * 36;
        float s = 0.0f;
#pragma unroll
        for (int d = 0; d < D_DIM; d++) {
            float v = er[SLOT(d)];
            s = fmaf(v, v, s);
        }
        sEsq[c] = s;
    }
    // ---- xsq + sum|x| + sBest init ----
    if (tid < 128) {
        const float* xr = sX + tid * 36;
        float s = 0.0f, a = 0.0f;
#pragma unroll
        for (int d = 0; d < D_DIM; d++) {
            float v = xr[SLOT(d)];
            s = fmaf(v, v, s);
            a += fabsf(v);
        }
        sXsq[tid] = s;
        sSab[tid] = a;
        sBest[tid] = 0xFFFFFFFFFFFFFFFFull;
    }
    __syncthreads();

    // ---- A fragments (4 x LDS.128 per thread) ----
    const int r0 = w * 16 + g;
    const int r1 = r0 + 8;
    float4 xa0 = *(const float4*)&sX[r0 * 36 + q4 * 8];
    float4 xa1 = *(const float4*)&sX[r0 * 36 + q4 * 8 + 4];
    float4 xb0 = *(const float4*)&sX[r1 * 36 + q4 * 8];
    float4 xb1 = *(const float4*)&sX[r1 * 36 + q4 * 8 + 4];
    float af0[4], af1[4], af2[4], af3[4];
    af0[0] = xa0.x; af2[0] = xa0.y; af0[1] = xa0.z; af2[1] = xa0.w;
    af0[2] = xa1.x; af2[2] = xa1.y; af0[3] = xa1.z; af2[3] = xa1.w;
    af1[0] = xb0.x; af3[0] = xb0.y; af1[1] = xb0.z; af3[1] = xb0.w;
    af1[2] = xb1.x; af3[2] = xb1.y; af1[3] = xb1.z; af3[3] = xb1.w;

    const float* peB = sE + g * 36 + q4 * 8;   // advances 288 per nt

#define MMA_TILE(nt)                                                              \
    float c0 = 0.0f, c1 = 0.0f, c2 = 0.0f, c3 = 0.0f;                             \
    {                                                                             \
        float4 e0 = *(const float4*)(peB + (nt) * 288);                           \
        float4 e1 = *(const float4*)(peB + (nt) * 288 + 4);                       \
        float bb[8] = {e0.x, e0.y, e0.z, e0.w, e1.x, e1.y, e1.z, e1.w};           \
        _Pragma("unroll")                                                         \
        for (int kt = 0; kt < 4; kt++) {                                          \
            asm volatile(                                                         \
                "mma.sync.aligned.m16n8k8.row.col.f32.tf32.tf32.f32 "             \
                "{%0,%1,%2,%3}, {%4,%5,%6,%7}, {%8,%9}, {%0,%1,%2,%3};"           \
                : "+f"(c0), "+f"(c1), "+f"(c2), "+f"(c3)                          \
                : "f"(af0[kt]), "f"(af1[kt]), "f"(af2[kt]), "f"(af3[kt]),         \
                  "f"(bb[2 * kt]), "f"(bb[2 * kt + 1]));                          \
        }                                                                         \
    }                                                                             \
    const int col0 = (nt) * 8 + q4 * 2;                                           \
    float2 e2 = *(const float2*)&sEsq[col0];                                      \
    float d00 = fmaf(c0, -2.0f, e2.x);                                            \
    float d01 = fmaf(c1, -2.0f, e2.y);                                            \
    float d10 = fmaf(c2, -2.0f, e2.x);                                            \
    float d11 = fmaf(c3, -2.0f, e2.y);

    // ---- seed phase: tiles 0..7 establish initial row minima (no queueing) ----
    float mn0 = FLT_BIG, mn1 = FLT_BIG;
#pragma unroll
    for (int nt = 0; nt < 8; nt++) {
        MMA_TILE(nt)
        mn0 = fminf(mn0, fminf(d00, d01));
        mn1 = fminf(mn1, fminf(d10, d11));
    }
    mn0 = fminf(mn0, __shfl_xor_sync(0xFFFFFFFFu, mn0, 1));
    mn0 = fminf(mn0, __shfl_xor_sync(0xFFFFFFFFu, mn0, 2));
    mn1 = fminf(mn1, __shfl_xor_sync(0xFFFFFFFFu, mn1, 1));
    mn1 = fminf(mn1, __shfl_xor_sync(0xFFFFFFFFu, mn1, 2));
    const float mg0 = fmaf(sSab[r0], MARG_COEF, MARG_ABS);
    const float mg1 = fmaf(sSab[r1], MARG_COEF, MARG_ABS);
    float thr0 = mn0 + mg0;
    float thr1 = mn1 + mg1;

    // ---- single full pass: queue hits, tighten thresholds locally (sound:
    //      thr monotonically decreases and stays >= final_tf32min + margin) ----
#pragma unroll 4
    for (int nt = 0; nt < 64; nt++) {
        MMA_TILE(nt)
        bool h00 = (d00 <= thr0), h01 = (d01 <= thr0);
        bool h10 = (d10 <= thr1), h11 = (d11 <= thr1);
        if (__ballot_sync(0xFFFFFFFFu, h00 | h01 | h10 | h11)) {
            if (h00) { int s = atomicAdd(&qn, 1); if (s < QCAP) sQ[s] = (r0 << 9) | col0; }
            if (h01) { int s = atomicAdd(&qn, 1); if (s < QCAP) sQ[s] = (r0 << 9) | (col0 + 1); }
            if (h10) { int s = atomicAdd(&qn, 1); if (s < QCAP) sQ[s] = (r1 << 9) | col0; }
            if (h11) { int s = atomicAdd(&qn, 1); if (s < QCAP) sQ[s] = (r1 << 9) | (col0 + 1); }
            mn0 = fminf(mn0, fminf(d00, d01));
            mn1 = fminf(mn1, fminf(d10, d11));
            thr0 = mn0 + mg0;
            thr1 = mn1 + mg1;
        }
    }
#undef MMA_TILE
    __syncthreads();

    // ---- exact fp32 recheck of queued candidates (reference-matching formula) ----
    {
        const int nq = (qn < QCAP) ? qn : QCAP;
        for (int i = tid; i < nq; i += 256) {
            const unsigned int e = sQ[i];
            const int row = e >> 9, code = e & 511;
            const float* xr = sX + row * 36;
            const float* er = sE + code * 36;
            float dot = 0.0f;
#pragma unroll
            for (int d = 0; d < D_DIM; d++)
                dot = fmaf(xr[SLOT(d)], er[SLOT(d)], dot);
            float dist = fmaf(dot, -2.0f, sXsq[row] + sEsq[code]);
            unsigned long long pk = ((unsigned long long)__float_as_uint(dist) << 32)
                                    | (unsigned int)code;
            atomicMin(&sBest[row], pk);
        }
    }
    __syncthreads();

    // ---- epilogue: outputs per position ----
    float lloss = 0.0f;
    if (tid < 128) {
        const int pp = tid;
        const int bi = (int)(sBest[pp] & 0xFFFFFFFFull);

        const int t = tile * 128 + pp;
        const int b = t >> 6, l = t & 63;
        out[OFF_IDX + (size_t)b * 256 + (size_t)n * 64 + l] = (float)bi;
        atomicAdd(&g_counts[n * M_CODES + bi], 1);

        float4* dwp = g_dw4 + ((size_t)n * M_CODES + bi) * 8;
        float*  zq  = out + OFF_ZQ + (size_t)b * 8192 + (size_t)n * 2048 + l;
        const float* xr = sX + pp * 36;
        const float* er = sE + bi * 36;
#pragma unroll
        for (int d4 = 0; d4 < 8; d4++) {
            float xv0 = xr[SLOT(d4 * 4 + 0)], q0 = er[SLOT(d4 * 4 + 0)];
            float xv1 = xr[SLOT(d4 * 4 + 1)], q1 = er[SLOT(d4 * 4 + 1)];
            float xv2 = xr[SLOT(d4 * 4 + 2)], q2 = er[SLOT(d4 * 4 + 2)];
            float xv3 = xr[SLOT(d4 * 4 + 3)], q3 = er[SLOT(d4 * 4 + 3)];
            zq[(d4 * 4 + 0) * 64] = __fsub_rn(__fadd_rn(q0, xv0), xv0);
            zq[(d4 * 4 + 1) * 64] = __fsub_rn(__fadd_rn(q1, xv1), xv1);
            zq[(d4 * 4 + 2) * 64] = __fsub_rn(__fadd_rn(q2, xv2), xv2);
            zq[(d4 * 4 + 3) * 64] = __fsub_rn(__fadd_rn(q3, xv3), xv3);
            float f0 = xv0 - q0, f1 = xv1 - q1, f2 = xv2 - q2, f3 = xv3 - q3;
            lloss = fmaf(f0, f0, lloss);
            lloss = fmaf(f1, f1, lloss);
            lloss = fmaf(f2, f2, lloss);
            lloss = fmaf(f3, f3, lloss);
            atomicAdd(dwp + d4, make_float4(xv0, xv1, xv2, xv3));
        }
    }

    // ---- CTA loss reduction -> one double atomic ----
#pragma unroll
    for (int o = 16; o > 0; o >>= 1) lloss += __shfl_down_sync(0xFFFFFFFFu, lloss, o);
    if (lane == 0) sWs[w] = lloss;
    __syncthreads();
    if (tid == 0) {
        double s = 0.0;
#pragma unroll
        for (int ww = 0; ww < 8; ww++) s += (double)sWs[ww];
        atomicAdd(&g_loss, s);
    }
}

// ---------------- kernel 2: EMA / Laplace / embedding / perplexity / loss ----------------
__global__ void vq_fin(const float* __restrict__ ema_c,
                       const float* __restrict__ ema_w,
                       float* __restrict__ out) {
    const int n = blockIdx.x;
    const int m = threadIdx.x;
    __shared__ float red[M_CODES];
    const float* g_dwf = (const float*)g_dw4;

    const float DECAY = 0.999f;
    const float OMD   = (float)(1.0 - 0.999);
    const float MEPS  = (float)(512.0 * 1e-5);

    float cnt  = (float)g_counts[n * M_CODES + m];
    float cnew = DECAY * ema_c[n * M_CODES + m] + OMD * cnt;

    red[m] = cnew;
    __syncthreads();
    for (int s = 256; s > 0; s >>= 1) {
        if (m < s) red[m] += red[m + s];
        __syncthreads();
    }
    float ntot = red[0];
    __syncthreads();

    float clap = (cnew + 1e-5f) / (ntot + MEPS) * ntot;
    out[OFF_CNT + (size_t)n * M_CODES + m] = clap;

#pragma unroll
    for (int d = 0; d < D_DIM; d++) {
        size_t idx = ((size_t)n * M_CODES + m) * D_DIM + d;
        float wv = DECAY * ema_w[idx] + OMD * g_dwf[idx];
        out[OFF_W + idx]   = wv;
        out[OFF_EMB + idx] = wv / clap;
    }

    float p    = cnt * (1.0f / 65536.0f);
    float term = p * logf(p + 1e-10f);
    red[m] = term;
    __syncthreads();
    for (int s = 256; s > 0; s >>= 1) {
        if (m < s) red[m] += red[m + s];
        __syncthreads();
    }
    if (m == 0) {
        atomicAdd(&out[OFF_PERP], expf(-red[0]));
        if (n == 0) out[OFF_LOSS] = (float)(0.25 * g_loss * (1.0 / 8388608.0));
    }
}

// ---------------- launch ----------------
extern "C" void kernel_launch(void* const* d_in, const int* in_sizes, int n_in,
                              void* d_out, int out_size) {
    const float* x     = (const float*)d_in[0];
    const float* emb   = (const float*)d_in[1];
    const float* ema_c = (const float*)d_in[2];
    const float* ema_w = (const float*)d_in[3];
    float* out = (float*)d_out;

    cudaFuncSetAttribute(vq_main, cudaFuncAttributeMaxDynamicSharedMemorySize, SMEM_BYTES);

    vq_zero<<<256, 256>>>(out);
    vq_main<<<dim3(T_POS / 128, N_CB), 256, SMEM_BYTES>>>(x, emb, out);
    vq_fin<<<N_CB, M_CODES>>>(ema_c, ema_w, out);
}

// round 9
// speedup vs baseline: 1.3471x; 1.3471x over previous
#include <cuda_runtime.h>
#include <cstdint>

// ---------------- problem constants ----------------
#define N_CB 4
#define M_CODES 512
#define D_DIM 32
#define T_POS 65536

// output layout (float32, reference tuple order, flattened+concatenated)
#define OFF_ZQ   0ULL
#define OFF_LOSS 8388608ULL
#define OFF_PERP 8388609ULL
#define OFF_IDX  8388610ULL
#define OFF_EMB  8650754ULL
#define OFF_CNT  8716290ULL
#define OFF_W    8718338ULL

// fragment-permuted slot: d = kt*8 + 4*h + q4  ->  slot = q4*8 + kt*2 + h
#define SLOT(d) (((d) & 3) * 8 + ((d) >> 3) * 2 + (((d) >> 2) & 1))

// ---------------- smem layout (float offsets), stride 36 rows ----------------
#define SXP_F   0        // x  [128 pos][36]  (permuted)   4608
#define SE_F    4608     // e  [512 code][36] (permuted)  18432
#define SESQ_F  23040    // esq[512]
#define SXSQ_F  23552    // xsq[128]
#define SSAB_F  23680    // sum|x| [128]
#define SBEST_F 23808    // u64[128] packed (dist,code)
#define SFL_F   24064    // flag list u32[128]
#define SWS_F   24192    // warp loss partials [8]
#define SMEM_FLOATS 24200
#define SMEM_BYTES (SMEM_FLOATS * 4)   // 96800 -> 2 CTAs/SM

#define FLT_BIG 3.402823466e38f
#define MARG_COEF 1.6e-4f
#define MARG_ABS  5e-5f
#define FCAP 128

// ---------------- scratch ----------------
__device__ int    g_counts[N_CB * M_CODES];
__device__ float4 g_dw4[N_CB * M_CODES * 8];
__device__ double g_loss;

// ---------------- kernel 0: zero scratch ----------------
__global__ void vq_zero(float* __restrict__ out) {
    int i = blockIdx.x * blockDim.x + threadIdx.x;
    float* dw = (float*)g_dw4;
    if (i < N_CB * M_CODES * D_DIM) dw[i] = 0.0f;
    if (i < N_CB * M_CODES)         g_counts[i] = 0;
    if (i == 0) { g_loss = 0.0; out[OFF_PERP] = 0.0f; }
}

// ---------------- kernel 1: single-sweep tf32 mma, branchless top-2, exact recheck ----------------
__global__ void __launch_bounds__(256) vq_main(const float* __restrict__ x,
                                               const float* __restrict__ emb,
                                               float* __restrict__ out) {
    extern __shared__ float sm[];
    __shared__ int fn;
    float* sX   = sm + SXP_F;
    float* sE   = sm + SE_F;
    float* sEsq = sm + SESQ_F;
    float* sXsq = sm + SXSQ_F;
    float* sSab = sm + SSAB_F;
    unsigned long long* sBest = (unsigned long long*)(sm + SBEST_F);
    unsigned int* sFl = (unsigned int*)(sm + SFL_F);
    float* sWs  = sm + SWS_F;

    const int n    = blockIdx.y;
    const int tile = blockIdx.x;
    const int tid  = threadIdx.x;
    const int w    = tid >> 5;
    const int lane = tid & 31;
    const int g    = lane >> 2;
    const int q4   = lane & 3;

    // ---- fill x tile (permuted layout) ----
    for (int i = tid; i < 128 * D_DIM; i += 256) {
        int d = i >> 7, p = i & 127;
        int t = tile * 128 + p;
        sX[p * 36 + SLOT(d)] = x[(size_t)(t >> 6) * 8192 + (size_t)n * 2048 + d * 64 + (t & 63)];
    }
    // ---- fill codebook (permuted layout) ----
    const float* en = emb + (size_t)n * M_CODES * D_DIM;
    for (int i = tid; i < M_CODES * D_DIM; i += 256) {
        int m = i >> 5, d = i & 31;
        sE[m * 36 + SLOT(d)] = en[i];
    }
    if (tid == 0) fn = 0;
    __syncthreads();

    // ---- esq: ascending-d fmaf chain (reference-matching) ----
    for (int c = tid; c < M_CODES; c += 256) {
        const float* er = sE + c * 36;
        float s = 0.0f;
#pragma unroll
        for (int d = 0; d < D_DIM; d++) {
            float v = er[SLOT(d)];
            s = fmaf(v, v, s);
        }
        sEsq[c] = s;
    }
    // ---- xsq + sum|x| + sBest init ----
    if (tid < 128) {
        const float* xr = sX + tid * 36;
        float s = 0.0f, a = 0.0f;
#pragma unroll
        for (int d = 0; d < D_DIM; d++) {
            float v = xr[SLOT(d)];
            s = fmaf(v, v, s);
            a += fabsf(v);
        }
        sXsq[tid] = s;
        sSab[tid] = a;
        sBest[tid] = 0xFFFFFFFFFFFFFFFFull;
    }
    __syncthreads();

    // ---- A fragments (4 x LDS.128 per thread) ----
    const int r0 = w * 16 + g;
    const int r1 = r0 + 8;
    float4 xa0 = *(const float4*)&sX[r0 * 36 + q4 * 8];
    float4 xa1 = *(const float4*)&sX[r0 * 36 + q4 * 8 + 4];
    float4 xb0 = *(const float4*)&sX[r1 * 36 + q4 * 8];
    float4 xb1 = *(const float4*)&sX[r1 * 36 + q4 * 8 + 4];
    float af0[4], af1[4], af2[4], af3[4];
    af0[0] = xa0.x; af2[0] = xa0.y; af0[1] = xa0.z; af2[1] = xa0.w;
    af0[2] = xa1.x; af2[2] = xa1.y; af0[3] = xa1.z; af2[3] = xa1.w;
    af1[0] = xb0.x; af3[0] = xb0.y; af1[1] = xb0.z; af3[1] = xb0.w;
    af1[2] = xb1.x; af3[2] = xb1.y; af1[3] = xb1.z; af3[3] = xb1.w;

    const float* peB = sE + g * 36 + q4 * 8;   // advances 288 per nt

    // ---- single branchless sweep: top-2 values + top-1 index per row ----
    float m1_0 = FLT_BIG, m2_0 = FLT_BIG, m1_1 = FLT_BIG, m2_1 = FLT_BIG;
    int   i1_0 = 0, i1_1 = 0;

#pragma unroll 4
    for (int nt = 0; nt < 64; nt++) {
        float c0 = 0.0f, c1 = 0.0f, c2 = 0.0f, c3 = 0.0f;
        {
            float4 e0 = *(const float4*)(peB + nt * 288);
            float4 e1 = *(const float4*)(peB + nt * 288 + 4);
            float bb[8] = {e0.x, e0.y, e0.z, e0.w, e1.x, e1.y, e1.z, e1.w};
#pragma unroll
            for (int kt = 0; kt < 4; kt++) {
                asm volatile(
                    "mma.sync.aligned.m16n8k8.row.col.f32.tf32.tf32.f32 "
                    "{%0,%1,%2,%3}, {%4,%5,%6,%7}, {%8,%9}, {%0,%1,%2,%3};"
                    : "+f"(c0), "+f"(c1), "+f"(c2), "+f"(c3)
                    : "f"(af0[kt]), "f"(af1[kt]), "f"(af2[kt]), "f"(af3[kt]),
                      "f"(bb[2 * kt]), "f"(bb[2 * kt + 1]));
            }
        }
        const int col0 = nt * 8 + q4 * 2;
        float2 e2 = *(const float2*)&sEsq[col0];
        float d00 = fmaf(c0, -2.0f, e2.x);
        float d01 = fmaf(c1, -2.0f, e2.y);
        float d10 = fmaf(c2, -2.0f, e2.x);
        float d11 = fmaf(c3, -2.0f, e2.y);

        // row 0: branchless top-2 + index of min
        {
            float lo = fminf(d00, d01);
            float hi = fmaxf(d00, d01);
            int  ilo = (d01 < d00) ? (col0 + 1) : col0;
            m2_0 = fminf(m2_0, fminf(hi, fmaxf(lo, m1_0)));
            i1_0 = (lo < m1_0) ? ilo : i1_0;
            m1_0 = fminf(m1_0, lo);
        }
        // row 1
        {
            float lo = fminf(d10, d11);
            float hi = fmaxf(d10, d11);
            int  ilo = (d11 < d10) ? (col0 + 1) : col0;
            m2_1 = fminf(m2_1, fminf(hi, fmaxf(lo, m1_1)));
            i1_1 = (lo < m1_1) ? ilo : i1_1;
            m1_1 = fminf(m1_1, lo);
        }
    }

    // save thread-local pre-merge state (recheck decisions use these)
    const float lm1_0 = m1_0, lm2_0 = m2_0, lm1_1 = m1_1, lm2_1 = m2_1;
    const int   li1_0 = i1_0, li1_1 = i1_1;

    // ---- merge across the 4 quad-threads of each row ----
#pragma unroll
    for (int o = 1; o <= 2; o <<= 1) {
        float om1 = __shfl_xor_sync(0xFFFFFFFFu, m1_0, o);
        float om2 = __shfl_xor_sync(0xFFFFFFFFu, m2_0, o);
        m2_0 = fminf(fminf(m2_0, om2), fmaxf(m1_0, om1));
        m1_0 = fminf(m1_0, om1);
        float pm1 = __shfl_xor_sync(0xFFFFFFFFu, m1_1, o);
        float pm2 = __shfl_xor_sync(0xFFFFFFFFu, m2_1, o);
        m2_1 = fminf(fminf(m2_1, pm2), fmaxf(m1_1, pm1));
        m1_1 = fminf(m1_1, pm1);
    }
    const float thr0 = m1_0 + fmaf(sSab[r0], MARG_COEF, MARG_ABS);
    const float thr1 = m1_1 + fmaf(sSab[r1], MARG_COEF, MARG_ABS);

    // ---- exact fp32 recheck of per-thread minima; flag ranges with 2nd-in-margin ----
#define EXACT_CHECK(row, code) {                                                  \
        const float* xr = sX + (row) * 36;                                        \
        const float* er = sE + (code) * 36;                                       \
        float dot = 0.0f;                                                         \
        _Pragma("unroll")                                                         \
        for (int d = 0; d < D_DIM; d++)                                           \
            dot = fmaf(xr[SLOT(d)], er[SLOT(d)], dot);                            \
        float dist = fmaf(dot, -2.0f, sXsq[row] + sEsq[code]);                    \
        unsigned long long pk = ((unsigned long long)__float_as_uint(dist) << 32) \
                                | (unsigned int)(code);                           \
        atomicMin(&sBest[row], pk);                                               \
    }

    if (lm1_0 <= thr0) EXACT_CHECK(r0, li1_0)
    if (lm1_1 <= thr1) EXACT_CHECK(r1, li1_1)
    if (lm2_0 <= thr0) { int s = atomicAdd(&fn, 1); if (s < FCAP) sFl[s] = (r0 << 2) | q4; }
    if (lm2_1 <= thr1) { int s = atomicAdd(&fn, 1); if (s < FCAP) sFl[s] = (r1 << 2) | q4; }
    __syncthreads();

    // ---- cooperative exact rescan of flagged (row, quad) 128-code ranges ----
    {
        const int nf = (fn < FCAP) ? fn : FCAP;
        for (int i = tid; i < nf * 128; i += 256) {
            const int e = i >> 7, k = i & 127;
            const unsigned int fl = sFl[e];
            const int row = fl >> 2, q = fl & 3;
            const int code = (k >> 1) * 8 + q * 2 + (k & 1);
            EXACT_CHECK(row, code)
        }
        // overflow fallback (practically never): rescan everything for safety
        if (fn > FCAP) {
            for (int i = tid; i < 128 * M_CODES; i += 256) {
                EXACT_CHECK(i >> 9, i & 511)
            }
        }
    }
#undef EXACT_CHECK
    __syncthreads();

    // ---- epilogue: outputs per position ----
    float lloss = 0.0f;
    if (tid < 128) {
        const int pp = tid;
        const int bi = (int)(sBest[pp] & 0xFFFFFFFFull);

        const int t = tile * 128 + pp;
        const int b = t >> 6, l = t & 63;
        out[OFF_IDX + (size_t)b * 256 + (size_t)n * 64 + l] = (float)bi;
        atomicAdd(&g_counts[n * M_CODES + bi], 1);

        float4* dwp = g_dw4 + ((size_t)n * M_CODES + bi) * 8;
        float*  zq  = out + OFF_ZQ + (size_t)b * 8192 + (size_t)n * 2048 + l;
        const float* xr = sX + pp * 36;
        const float* er = sE + bi * 36;
#pragma unroll
        for (int d4 = 0; d4 < 8; d4++) {
            float xv0 = xr[SLOT(d4 * 4 + 0)], q0 = er[SLOT(d4 * 4 + 0)];
            float xv1 = xr[SLOT(d4 * 4 + 1)], q1 = er[SLOT(d4 * 4 + 1)];
            float xv2 = xr[SLOT(d4 * 4 + 2)], q2 = er[SLOT(d4 * 4 + 2)];
            float xv3 = xr[SLOT(d4 * 4 + 3)], q3 = er[SLOT(d4 * 4 + 3)];
            zq[(d4 * 4 + 0) * 64] = __fsub_rn(__fadd_rn(q0, xv0), xv0);
            zq[(d4 * 4 + 1) * 64] = __fsub_rn(__fadd_rn(q1, xv1), xv1);
            zq[(d4 * 4 + 2) * 64] = __fsub_rn(__fadd_rn(q2, xv2), xv2);
            zq[(d4 * 4 + 3) * 64] = __fsub_rn(__fadd_rn(q3, xv3), xv3);
            float f0 = xv0 - q0, f1 = xv1 - q1, f2 = xv2 - q2, f3 = xv3 - q3;
            lloss = fmaf(f0, f0, lloss);
            lloss = fmaf(f1, f1, lloss);
            lloss = fmaf(f2, f2, lloss);
            lloss = fmaf(f3, f3, lloss);
            atomicAdd(dwp + d4, make_float4(xv0, xv1, xv2, xv3));
        }
    }

    // ---- CTA loss reduction -> one double atomic ----
#pragma unroll
    for (int o = 16; o > 0; o >>= 1) lloss += __shfl_down_sync(0xFFFFFFFFu, lloss, o);
    if (lane == 0) sWs[w] = lloss;
    __syncthreads();
    if (tid == 0) {
        double s = 0.0;
#pragma unroll
        for (int ww = 0; ww < 8; ww++) s += (double)sWs[ww];
        atomicAdd(&g_loss, s);
    }
}

// ---------------- kernel 2: EMA / Laplace / embedding / perplexity / loss ----------------
__global__ void vq_fin(const float* __restrict__ ema_c,
                       const float* __restrict__ ema_w,
                       float* __restrict__ out) {
    const int n = blockIdx.x;
    const int m = threadIdx.x;
    __shared__ float red[M_CODES];
    const float* g_dwf = (const float*)g_dw4;

    const float DECAY = 0.999f;
    const float OMD   = (float)(1.0 - 0.999);
    const float MEPS  = (float)(512.0 * 1e-5);

    float cnt  = (float)g_counts[n * M_CODES + m];
    float cnew = DECAY * ema_c[n * M_CODES + m] + OMD * cnt;

    red[m] = cnew;
    __syncthreads();
    for (int s = 256; s > 0; s >>= 1) {
        if (m < s) red[m] += red[m + s];
        __syncthreads();
    }
    float ntot = red[0];
    __syncthreads();

    float clap = (cnew + 1e-5f) / (ntot + MEPS) * ntot;
    out[OFF_CNT + (size_t)n * M_CODES + m] = clap;

#pragma unroll
    for (int d = 0; d < D_DIM; d++) {
        size_t idx = ((size_t)n * M_CODES + m) * D_DIM + d;
        float wv = DECAY * ema_w[idx] + OMD * g_dwf[idx];
        out[OFF_W + idx]   = wv;
        out[OFF_EMB + idx] = wv / clap;
    }

    float p    = cnt * (1.0f / 65536.0f);
    float term = p * logf(p + 1e-10f);
    red[m] = term;
    __syncthreads();
    for (int s = 256; s > 0; s >>= 1) {
        if (m < s) red[m] += red[m + s];
        __syncthreads();
    }
    if (m == 0) {
        atomicAdd(&out[OFF_PERP], expf(-red[0]));
        if (n == 0) out[OFF_LOSS] = (float)(0.25 * g_loss * (1.0 / 8388608.0));
    }
}

// ---------------- launch ----------------
extern "C" void kernel_launch(void* const* d_in, const int* in_sizes, int n_in,
                              void* d_out, int out_size) {
    const float* x     = (const float*)d_in[0];
    const float* emb   = (const float*)d_in[1];
    const float* ema_c = (const float*)d_in[2];
    const float* ema_w = (const float*)d_in[3];
    float* out = (float*)d_out;

    cudaFuncSetAttribute(vq_main, cudaFuncAttributeMaxDynamicSharedMemorySize, SMEM_BYTES);

    vq_zero<<<256, 256>>>(out);
    vq_main<<<dim3(T_POS / 128, N_CB), 256, SMEM_BYTES>>>(x, emb, out);
    vq_fin<<<N_CB, M_CODES>>>(ema_c, ema_w, out);
}